// round 4
// baseline (speedup 1.0000x reference)
#include <cuda_runtime.h>
#include <cstdint>

#define N_NODES 100000
#define N_EDGES 1600000
#define DIM     128
#define T_NODES 4096
#define P_PAIRS 131072
#define HP      256
#define DOUT    128
#define ZDIM    64

// ---------------- scratch (static device globals; no allocation) ----------------
__device__ int   g_cnt[N_NODES];
__device__ int   g_rowptr[N_NODES + 1];
__device__ int   g_cursor[N_NODES];
__device__ int   g_col[N_EDGES];
__device__ float g_invdeg[N_NODES];
__device__ unsigned char g_flag[N_NODES];
__device__ float g_pe[N_NODES * 4];
__device__ float g_zb[HP];
__device__ float g_wf[DIM * HP];                    // W2c @ Wp1[0:128]
__device__ float g_buf1[(size_t)N_NODES * DIM];
__device__ float g_buf2[(size_t)N_NODES * DIM];
__device__ float g_tbuf[(size_t)T_NODES * DIM];
__device__ float g_hidden[(size_t)P_PAIRS * HP];

// ---------------- f32x2 packed-FMA helpers ----------------
__device__ __forceinline__ unsigned long long dup2(float v) {
    unsigned long long r;
    asm("mov.b64 %0, {%1, %1};" : "=l"(r) : "f"(v));
    return r;
}
__device__ __forceinline__ void ffma2(unsigned long long& acc, unsigned long long a,
                                      unsigned long long b) {
    asm("fma.rn.f32x2 %0, %1, %2, %0;" : "+l"(acc) : "l"(a), "l"(b));
}
__device__ __forceinline__ float2 unpack2(unsigned long long v) {
    float2 f;
    asm("mov.b64 {%0, %1}, %2;" : "=f"(f.x), "=f"(f.y) : "l"(v));
    return f;
}

// ---------------- CSR build ----------------
__global__ void k_zero_cnt() {
    int i = blockIdx.x * blockDim.x + threadIdx.x;
    if (i < N_NODES) { g_cnt[i] = 0; g_flag[i] = 0; }
}

__global__ void k_count(const int* __restrict__ dst) {
    int e = blockIdx.x * blockDim.x + threadIdx.x;
    if (e < N_EDGES) atomicAdd(&g_cnt[dst[e]], 1);
}

__global__ void k_scan() {
    __shared__ int sums[1024];
    const int CH = (N_NODES + 1024) / 1024;
    int t = threadIdx.x;
    int base = t * CH;
    int s = 0;
    for (int i = 0; i < CH; i++) {
        int idx = base + i;
        if (idx < N_NODES) s += g_cnt[idx];
    }
    sums[t] = s;
    __syncthreads();
    for (int off = 1; off < 1024; off <<= 1) {
        int v = (t >= off) ? sums[t - off] : 0;
        __syncthreads();
        sums[t] += v;
        __syncthreads();
    }
    int run = sums[t] - s;
    for (int i = 0; i < CH; i++) {
        int idx = base + i;
        if (idx <= N_NODES) g_rowptr[idx] = run;
        if (idx < N_NODES) run += g_cnt[idx];
    }
}

__global__ void k_prep() {
    int i = blockIdx.x * blockDim.x + threadIdx.x;
    if (i < N_NODES) {
        g_cursor[i] = g_rowptr[i];
        int c = g_cnt[i];
        g_invdeg[i] = 1.0f / (float)(c > 0 ? c : 1);
    }
}

__global__ void k_fill(const int* __restrict__ src, const int* __restrict__ dst) {
    int e = blockIdx.x * blockDim.x + threadIdx.x;
    if (e < N_EDGES) {
        int pos = atomicAdd(&g_cursor[dst[e]], 1);
        g_col[pos] = src[e];
    }
}

// mark nodes whose context aggregation is actually consumed by the predictor
__global__ void k_flag(const int* __restrict__ pair_s, const float* __restrict__ mask) {
    int i = blockIdx.x * blockDim.x + threadIdx.x;
    if (i < P_PAIRS && mask[i] != 0.f) g_flag[pair_s[i]] = 1;
}

// ---------------- tiny precomputes ----------------
__global__ void k_pe(const float* __restrict__ pos_enc, const float* __restrict__ Wpe) {
    int n = blockIdx.x * blockDim.x + threadIdx.x;
    if (n >= N_NODES) return;
    float4 p = *(const float4*)&pos_enc[n * 4];
#pragma unroll
    for (int i = 0; i < 4; i++) {
        g_pe[n * 4 + i] = p.x * Wpe[i * 4 + 0] + p.y * Wpe[i * 4 + 1] +
                          p.z * Wpe[i * 4 + 2] + p.w * Wpe[i * 4 + 3];
    }
}

__global__ void k_zb(const float* __restrict__ z, const float* __restrict__ Wp1,
                     const float* __restrict__ bp1) {
    int j = threadIdx.x;
    float acc = bp1[j];
    for (int i = 0; i < ZDIM; i++) acc = fmaf(z[i], Wp1[(128 + i) * HP + j], acc);
    g_zb[j] = acc;
}

__global__ void k_wf(const float* __restrict__ W2c, const float* __restrict__ Wp1) {
    int i = blockIdx.x;
    int j = threadIdx.x;
    float acc = 0.f;
    for (int d = 0; d < DIM; d++) acc = fmaf(W2c[i * DIM + d], Wp1[d * HP + j], acc);
    g_wf[i * HP + j] = acc;
}

// ---------------- SGEMM via FFMA2: C[M,128] = (relu?)(A[M,128] @ B[128,128]) -------
// 128x128 block tile, 256 threads, 8x8 thread tile (paired columns), f32x2 FMAs.
__global__ void k_gemm128(const float* __restrict__ A, const float* __restrict__ B,
                          float* __restrict__ C, int M, int relu) {
    __shared__ __align__(16) float As[128 * 16];
    __shared__ __align__(16) float Bs[16 * 128];
    int m0 = blockIdx.x * 128;
    int tid = threadIdx.x;
    int ty = tid >> 4, tx = tid & 15;      // 16x16 thread grid

    unsigned long long acc2[8][4];
#pragma unroll
    for (int r = 0; r < 8; r++)
#pragma unroll
        for (int c = 0; c < 4; c++) acc2[r][c] = 0ull;

    int arow = tid >> 1, akq = (tid & 1) * 8;   // A: 128 rows x 16 k
    int brow = tid >> 4, bcq = (tid & 15) * 8;  // B: 16 k x 128 cols

    float4 ra0, ra1, rb0, rb1;
    {
        int grow = m0 + arow;
        if (grow < M) {
            ra0 = *(const float4*)&A[(size_t)grow * 128 + akq];
            ra1 = *(const float4*)&A[(size_t)grow * 128 + akq + 4];
        } else {
            ra0 = make_float4(0.f, 0.f, 0.f, 0.f); ra1 = ra0;
        }
        rb0 = *(const float4*)&B[(size_t)brow * 128 + bcq];
        rb1 = *(const float4*)&B[(size_t)brow * 128 + bcq + 4];
    }

    for (int ch = 0; ch < 8; ch++) {
        __syncthreads();
        *(float4*)&As[arow * 16 + akq]     = ra0;
        *(float4*)&As[arow * 16 + akq + 4] = ra1;
        *(float4*)&Bs[brow * 128 + bcq]     = rb0;
        *(float4*)&Bs[brow * 128 + bcq + 4] = rb1;
        __syncthreads();
        if (ch < 7) {
            int kc = (ch + 1) * 16;
            int grow = m0 + arow;
            if (grow < M) {
                ra0 = *(const float4*)&A[(size_t)grow * 128 + kc + akq];
                ra1 = *(const float4*)&A[(size_t)grow * 128 + kc + akq + 4];
            } else {
                ra0 = make_float4(0.f, 0.f, 0.f, 0.f); ra1 = ra0;
            }
            rb0 = *(const float4*)&B[(size_t)(kc + brow) * 128 + bcq];
            rb1 = *(const float4*)&B[(size_t)(kc + brow) * 128 + bcq + 4];
        }
#pragma unroll
        for (int k = 0; k < 16; k++) {
            unsigned long long b2[4];
#pragma unroll
            for (int cp = 0; cp < 4; cp++)
                b2[cp] = *(const unsigned long long*)&Bs[k * 128 + 2 * tx + 32 * cp];
#pragma unroll
            for (int r = 0; r < 8; r++) {
                unsigned long long a2 = dup2(As[(ty * 8 + r) * 16 + k]);
#pragma unroll
                for (int cp = 0; cp < 4; cp++) ffma2(acc2[r][cp], a2, b2[cp]);
            }
        }
    }

#pragma unroll
    for (int r = 0; r < 8; r++) {
        int row = m0 + ty * 8 + r;
        if (row < M) {
#pragma unroll
            for (int cp = 0; cp < 4; cp++) {
                float2 v = unpack2(acc2[r][cp]);
                if (relu) { v.x = fmaxf(v.x, 0.f); v.y = fmaxf(v.y, 0.f); }
                *(float2*)&C[(size_t)row * 128 + 2 * tx + 32 * cp] = v;
            }
        }
    }
}

// ---------------- CSR gather-aggregation: warp per node, float4 lanes ----------------
__device__ __forceinline__ void agg_node(const float* __restrict__ in, int n, int lane,
                                         float4& r) {
    int s = g_rowptr[n], e = g_rowptr[n + 1];
    float4 a0 = make_float4(0.f, 0.f, 0.f, 0.f), a1 = a0, a2 = a0, a3 = a0;
    int i = s;
    for (; i + 4 <= e; i += 4) {
        int c0 = g_col[i], c1 = g_col[i + 1], c2 = g_col[i + 2], c3 = g_col[i + 3];
        float4 v0 = *(const float4*)&in[(size_t)c0 * 128 + lane * 4];
        float4 v1 = *(const float4*)&in[(size_t)c1 * 128 + lane * 4];
        float4 v2 = *(const float4*)&in[(size_t)c2 * 128 + lane * 4];
        float4 v3 = *(const float4*)&in[(size_t)c3 * 128 + lane * 4];
        a0.x += v0.x; a0.y += v0.y; a0.z += v0.z; a0.w += v0.w;
        a1.x += v1.x; a1.y += v1.y; a1.z += v1.z; a1.w += v1.w;
        a2.x += v2.x; a2.y += v2.y; a2.z += v2.z; a2.w += v2.w;
        a3.x += v3.x; a3.y += v3.y; a3.z += v3.z; a3.w += v3.w;
    }
    for (; i < e; i++) {
        int c = g_col[i];
        float4 v = *(const float4*)&in[(size_t)c * 128 + lane * 4];
        a0.x += v.x; a0.y += v.y; a0.z += v.z; a0.w += v.w;
    }
    float inv = g_invdeg[n];
    r.x = (a0.x + a1.x + a2.x + a3.x) * inv;
    r.y = (a0.y + a1.y + a2.y + a3.y) * inv;
    r.z = (a0.z + a1.z + a2.z + a3.z) * inv;
    r.w = (a0.w + a1.w + a2.w + a3.w) * inv;
}

__global__ void k_agg(const float* __restrict__ in, float* __restrict__ out) {
    int n = blockIdx.x * 8 + (threadIdx.x >> 5);
    if (n >= N_NODES) return;
    int lane = threadIdx.x & 31;
    float4 r;
    agg_node(in, n, lane, r);
    *(float4*)&out[(size_t)n * 128 + lane * 4] = r;
}

// aggregate only nodes flagged as predictor sources
__global__ void k_agg_flagged(const float* __restrict__ in, float* __restrict__ out) {
    int n = blockIdx.x * 8 + (threadIdx.x >> 5);
    if (n >= N_NODES) return;
    if (!g_flag[n]) return;
    int lane = threadIdx.x & 31;
    float4 r;
    agg_node(in, n, lane, r);
    *(float4*)&out[(size_t)n * 128 + lane * 4] = r;
}

__global__ void k_agg_target(const float* __restrict__ in, const int* __restrict__ tgt,
                             float* __restrict__ out) {
    int b = blockIdx.x * 8 + (threadIdx.x >> 5);
    if (b >= T_NODES) return;
    int lane = threadIdx.x & 31;
    int n = tgt[b];
    float4 r;
    agg_node(in, n, lane, r);
    *(float4*)&out[(size_t)b * 128 + lane * 4] = r;
}

// ---------------- predictor stage 1 (FFMA2): hidden = relu(m[pair_s]@Wf + pe + zb) --
// 64-row tile, 256 threads, 8x8 thread tile (paired columns 2cg+64cp).
__global__ void k_pred1(const float* __restrict__ m, const int* __restrict__ pair_s,
                        const int* __restrict__ pair_t, const int* __restrict__ tgt,
                        const float* __restrict__ mask, const float* __restrict__ Wp1) {
    int r0 = blockIdx.x * 64;
    int tid = threadIdx.x;
    int any = __syncthreads_or(tid < 64 && mask[r0 + tid] != 0.f);
    if (!any) return;  // pred2 zero-fills these rows

    __shared__ __align__(16) float feats[64 * 140];
    __shared__ __align__(16) float ws[8 * 256];

#pragma unroll
    for (int i = 0; i < 8; i++) {
        int idx = tid + i * 256;
        int r = idx >> 5, q = (idx & 31) << 2;
        int sN = pair_s[r0 + r];
        *(float4*)&feats[r * 140 + q] = *(const float4*)&m[(size_t)sN * 128 + q];
    }
    if (tid < 64) {
        int sN = pair_s[r0 + tid];
        int tN = tgt[pair_t[r0 + tid]];
        *(float4*)&feats[tid * 140 + 128] = *(const float4*)&g_pe[sN * 4];
        *(float4*)&feats[tid * 140 + 132] = *(const float4*)&g_pe[tN * 4];
    }

    int rg = tid >> 5, cg = tid & 31;
    unsigned long long acc2[8][4];
#pragma unroll
    for (int r = 0; r < 8; r++)
#pragma unroll
        for (int c = 0; c < 4; c++) acc2[r][c] = 0ull;

    for (int ch = 0; ch < 17; ch++) {
        {
            int kk = tid >> 5, j = (tid & 31) << 3;
            const float* src = (ch < 16) ? &g_wf[(ch * 8 + kk) * 256 + j]
                                         : &Wp1[(192 + kk) * 256 + j];
            *(float4*)&ws[kk * 256 + j]     = *(const float4*)src;
            *(float4*)&ws[kk * 256 + j + 4] = *(const float4*)(src + 4);
        }
        __syncthreads();
#pragma unroll
        for (int kk = 0; kk < 8; kk++) {
            int k = ch * 8 + kk;
            unsigned long long b2[4];
#pragma unroll
            for (int cp = 0; cp < 4; cp++)
                b2[cp] = *(const unsigned long long*)&ws[kk * 256 + 2 * cg + 64 * cp];
#pragma unroll
            for (int r = 0; r < 8; r++) {
                unsigned long long a2 = dup2(feats[(rg * 8 + r) * 140 + k]);
#pragma unroll
                for (int cp = 0; cp < 4; cp++) ffma2(acc2[r][cp], a2, b2[cp]);
            }
        }
        __syncthreads();
    }

#pragma unroll
    for (int cp = 0; cp < 4; cp++) {
        float2 zbv = *(const float2*)&g_zb[2 * cg + 64 * cp];
#pragma unroll
        for (int r = 0; r < 8; r++) {
            int row = r0 + rg * 8 + r;
            float2 v = unpack2(acc2[r][cp]);
            v.x = fmaxf(v.x + zbv.x, 0.f);
            v.y = fmaxf(v.y + zbv.y, 0.f);
            *(float2*)&g_hidden[(size_t)row * 256 + 2 * cg + 64 * cp] = v;
        }
    }
}

// ---------------- predictor stage 2 (FFMA2): pred = (hidden @ Wp2 + bp2) * mask -----
// 64-row tile, 256 threads, 8x4 thread tile (paired columns 2cg+64cp, cp<2).
__global__ void k_pred2(const float* __restrict__ Wp2, const float* __restrict__ bp2,
                        const float* __restrict__ mask, float* __restrict__ out) {
    int r0 = blockIdx.x * 64;
    int tid = threadIdx.x;
    __shared__ float ms[64];
    if (tid < 64) ms[tid] = mask[r0 + tid];
    int any = __syncthreads_or(tid < 64 && mask[r0 + tid] != 0.f);
    if (!any) {
        float4 zero = make_float4(0.f, 0.f, 0.f, 0.f);
#pragma unroll
        for (int i = 0; i < 8; i++) {
            int idx = tid + i * 256;
            *(float4*)&out[(size_t)r0 * 128 + idx * 4] = zero;
        }
        return;
    }

    __shared__ __align__(16) float As[64 * 17];
    __shared__ __align__(16) float ws2[16 * 128];

    int rg = tid >> 5, cg = tid & 31;
    unsigned long long acc2[8][2];
#pragma unroll
    for (int r = 0; r < 8; r++) { acc2[r][0] = 0ull; acc2[r][1] = 0ull; }

    for (int ch = 0; ch < 16; ch++) {
        {
            int r = tid >> 2, kq = (tid & 3) << 2;
            float4 v = *(const float4*)&g_hidden[(size_t)(r0 + r) * 256 + ch * 16 + kq];
            As[r * 17 + kq]     = v.x;
            As[r * 17 + kq + 1] = v.y;
            As[r * 17 + kq + 2] = v.z;
            As[r * 17 + kq + 3] = v.w;
        }
#pragma unroll
        for (int h = 0; h < 2; h++) {
            int kk = (tid >> 5) + h * 8;
            int j = tid & 31;
#pragma unroll
            for (int q = 0; q < 4; q++)
                ws2[kk * 128 + j + 32 * q] = Wp2[(size_t)(ch * 16 + kk) * 128 + j + 32 * q];
        }
        __syncthreads();
#pragma unroll
        for (int kk = 0; kk < 16; kk++) {
            unsigned long long b2[2];
            b2[0] = *(const unsigned long long*)&ws2[kk * 128 + 2 * cg];
            b2[1] = *(const unsigned long long*)&ws2[kk * 128 + 2 * cg + 64];
#pragma unroll
            for (int r = 0; r < 8; r++) {
                unsigned long long a2 = dup2(As[(rg * 8 + r) * 17 + kk]);
                ffma2(acc2[r][0], a2, b2[0]);
                ffma2(acc2[r][1], a2, b2[1]);
            }
        }
        __syncthreads();
    }

#pragma unroll
    for (int cp = 0; cp < 2; cp++) {
        float2 bb = *(const float2*)&bp2[2 * cg + 64 * cp];
#pragma unroll
        for (int r = 0; r < 8; r++) {
            int lr = rg * 8 + r;
            float2 v = unpack2(acc2[r][cp]);
            v.x = (v.x + bb.x) * ms[lr];
            v.y = (v.y + bb.y) * ms[lr];
            *(float2*)&out[(size_t)(r0 + lr) * 128 + 2 * cg + 64 * cp] = v;
        }
    }
}

// ---------------- launch ----------------
extern "C" void kernel_launch(void* const* d_in, const int* in_sizes, int n_in,
                              void* d_out, int out_size) {
    const float* x            = (const float*)d_in[0];
    const float* masked_x     = (const float*)d_in[1];
    const float* pos_enc      = (const float*)d_in[2];
    const int*   edge_src     = (const int*)d_in[3];
    const int*   edge_dst     = (const int*)d_in[4];
    const int*   target_nodes = (const int*)d_in[5];
    const int*   pair_t       = (const int*)d_in[6];
    const int*   pair_s       = (const int*)d_in[7];
    const float* pair_mask    = (const float*)d_in[8];
    const float* W1t          = (const float*)d_in[9];
    const float* W2t          = (const float*)d_in[10];
    const float* W1c          = (const float*)d_in[11];
    const float* W2c          = (const float*)d_in[12];
    const float* Wpe          = (const float*)d_in[13];
    const float* z            = (const float*)d_in[14];
    const float* Wp1          = (const float*)d_in[15];
    const float* bp1          = (const float*)d_in[16];
    const float* Wp2          = (const float*)d_in[17];
    const float* bp2          = (const float*)d_in[18];
    float* out = (float*)d_out;

    float *buf1, *buf2, *tbuf;
    cudaGetSymbolAddress((void**)&buf1, g_buf1);
    cudaGetSymbolAddress((void**)&buf2, g_buf2);
    cudaGetSymbolAddress((void**)&tbuf, g_tbuf);

    const int TPB = 256;
    int gridN = (N_NODES + TPB - 1) / TPB;
    int gridE = (N_EDGES + TPB - 1) / TPB;
    int gridM = (N_NODES + 127) / 128;
    int gridA = (N_NODES + 7) / 8;

    // CSR build + predictor-source flags
    k_zero_cnt<<<gridN, TPB>>>();
    k_count<<<gridE, TPB>>>(edge_dst);
    k_scan<<<1, 1024>>>();
    k_prep<<<gridN, TPB>>>();
    k_fill<<<gridE, TPB>>>(edge_src, edge_dst);
    k_flag<<<P_PAIRS / TPB, TPB>>>(pair_s, pair_mask);

    // tiny precomputes
    k_pe<<<gridN, TPB>>>(pos_enc, Wpe);
    k_zb<<<1, HP>>>(z, Wp1, bp1);
    k_wf<<<DIM, HP>>>(W2c, Wp1);

    // target GCN: agg -> GEMM(relu) -> target-agg -> tiny GEMM straight to out
    k_agg<<<gridA, 256>>>(x, buf1);
    k_gemm128<<<gridM, 256>>>(buf1, W1t, buf2, N_NODES, 1);
    k_agg_target<<<(T_NODES + 7) / 8, 256>>>(buf2, target_nodes, tbuf);
    k_gemm128<<<T_NODES / 128, 256>>>(tbuf, W2t, out + (size_t)P_PAIRS * DOUT,
                                      T_NODES, 0);

    // context GCN: agg -> GEMM(relu) -> flagged agg (2nd GEMM folded into Wf)
    k_agg<<<gridA, 256>>>(masked_x, buf1);
    k_gemm128<<<gridM, 256>>>(buf1, W1c, buf2, N_NODES, 1);
    k_agg_flagged<<<gridA, 256>>>(buf2, buf1);   // m -> buf1 (flagged nodes only)

    // predictor MLP (64-row tiles, mask-tile skipping)
    k_pred1<<<P_PAIRS / 64, 256>>>(buf1, pair_s, pair_t, target_nodes, pair_mask, Wp1);
    k_pred2<<<P_PAIRS / 64, 256>>>(Wp2, bp2, pair_mask, out);
}

// round 5
// speedup vs baseline: 1.4104x; 1.4104x over previous
#include <cuda_runtime.h>
#include <cstdint>

#define N_NODES 100000
#define N_EDGES 1600000
#define DIM     128
#define T_NODES 4096
#define P_PAIRS 131072
#define HP      256
#define DOUT    128
#define ZDIM    64

// ---------------- scratch (static device globals; no allocation) ----------------
__device__ int   g_cnt[N_NODES];
__device__ int   g_rowptr[N_NODES + 1];
__device__ int   g_cursor[N_NODES];
__device__ int   g_col[N_EDGES];
__device__ float g_invdeg[N_NODES];
__device__ unsigned char g_flag[N_NODES];
__device__ float g_pe[N_NODES * 4];
__device__ float g_zb[HP];
__device__ float g_wf[DIM * HP];                    // W2c @ Wp1[0:128]
__device__ float g_buf1[(size_t)N_NODES * DIM];
__device__ float g_buf2[(size_t)N_NODES * DIM];
__device__ float g_tbuf[(size_t)T_NODES * DIM];
__device__ float g_hidden[(size_t)P_PAIRS * HP];

// ---------------- tf32 helpers ----------------
__device__ __forceinline__ unsigned f2tf(float f) {
    unsigned u;
    asm("cvt.rna.tf32.f32 %0, %1;" : "=r"(u) : "f"(f));
    return u;
}
__device__ __forceinline__ void mma8(float* c, const unsigned* a, const unsigned* b) {
    asm volatile(
        "mma.sync.aligned.m16n8k8.row.col.f32.tf32.tf32.f32 "
        "{%0,%1,%2,%3},{%4,%5,%6,%7},{%8,%9},{%0,%1,%2,%3};"
        : "+f"(c[0]), "+f"(c[1]), "+f"(c[2]), "+f"(c[3])
        : "r"(a[0]), "r"(a[1]), "r"(a[2]), "r"(a[3]), "r"(b[0]), "r"(b[1]));
}

// ---------------- CSR build ----------------
__global__ void k_zero_cnt() {
    int i = blockIdx.x * blockDim.x + threadIdx.x;
    if (i < N_NODES) { g_cnt[i] = 0; g_flag[i] = 0; }
}

__global__ void k_count(const int* __restrict__ dst) {
    int e = blockIdx.x * blockDim.x + threadIdx.x;
    if (e < N_EDGES) atomicAdd(&g_cnt[dst[e]], 1);
}

__global__ void k_scan() {
    __shared__ int sums[1024];
    const int CH = (N_NODES + 1024) / 1024;
    int t = threadIdx.x;
    int base = t * CH;
    int s = 0;
    for (int i = 0; i < CH; i++) {
        int idx = base + i;
        if (idx < N_NODES) s += g_cnt[idx];
    }
    sums[t] = s;
    __syncthreads();
    for (int off = 1; off < 1024; off <<= 1) {
        int v = (t >= off) ? sums[t - off] : 0;
        __syncthreads();
        sums[t] += v;
        __syncthreads();
    }
    int run = sums[t] - s;
    for (int i = 0; i < CH; i++) {
        int idx = base + i;
        if (idx <= N_NODES) g_rowptr[idx] = run;
        if (idx < N_NODES) run += g_cnt[idx];
    }
}

__global__ void k_prep() {
    int i = blockIdx.x * blockDim.x + threadIdx.x;
    if (i < N_NODES) {
        g_cursor[i] = g_rowptr[i];
        int c = g_cnt[i];
        g_invdeg[i] = 1.0f / (float)(c > 0 ? c : 1);
    }
}

__global__ void k_fill(const int* __restrict__ src, const int* __restrict__ dst) {
    int e = blockIdx.x * blockDim.x + threadIdx.x;
    if (e < N_EDGES) {
        int pos = atomicAdd(&g_cursor[dst[e]], 1);
        g_col[pos] = src[e];
    }
}

__global__ void k_flag(const int* __restrict__ pair_s, const float* __restrict__ mask) {
    int i = blockIdx.x * blockDim.x + threadIdx.x;
    if (i < P_PAIRS && mask[i] != 0.f) g_flag[pair_s[i]] = 1;
}

// ---------------- tiny precomputes ----------------
__global__ void k_pe(const float* __restrict__ pos_enc, const float* __restrict__ Wpe) {
    int n = blockIdx.x * blockDim.x + threadIdx.x;
    if (n >= N_NODES) return;
    float4 p = *(const float4*)&pos_enc[n * 4];
#pragma unroll
    for (int i = 0; i < 4; i++) {
        g_pe[n * 4 + i] = p.x * Wpe[i * 4 + 0] + p.y * Wpe[i * 4 + 1] +
                          p.z * Wpe[i * 4 + 2] + p.w * Wpe[i * 4 + 3];
    }
}

__global__ void k_zb(const float* __restrict__ z, const float* __restrict__ Wp1,
                     const float* __restrict__ bp1) {
    int j = threadIdx.x;
    float acc = bp1[j];
    for (int i = 0; i < ZDIM; i++) acc = fmaf(z[i], Wp1[(128 + i) * HP + j], acc);
    g_zb[j] = acc;
}

__global__ void k_wf(const float* __restrict__ W2c, const float* __restrict__ Wp1) {
    int i = blockIdx.x;
    int j = threadIdx.x;
    float acc = 0.f;
    for (int d = 0; d < DIM; d++) acc = fmaf(W2c[i * DIM + d], Wp1[d * HP + j], acc);
    g_wf[i * HP + j] = acc;
}

// ---------------- tf32 GEMM: C[M,128] = (relu?)(A[M,128] @ B[128,128]) -------------
// 128x128 block, 256 threads (8 warps as 4x2), warp tile 32x64, mma m16n8k8.
#define AS_STR 36
#define BS_STR 136
__global__ void __launch_bounds__(256)
k_gemm_tf32(const float* __restrict__ A, const float* __restrict__ B,
            float* __restrict__ C, int M, int relu) {
    __shared__ unsigned As[128 * AS_STR];
    __shared__ unsigned Bs[32 * BS_STR];
    int m0 = blockIdx.x * 128;
    int tid = threadIdx.x;
    int lane = tid & 31, wid = tid >> 5;
    int wm = wid & 3, wn = wid >> 2;      // rows wm*32, cols wn*64
    int gid = lane >> 2, tig = lane & 3;

    float c[2][8][4];
#pragma unroll
    for (int mt = 0; mt < 2; mt++)
#pragma unroll
        for (int nt = 0; nt < 8; nt++)
#pragma unroll
            for (int q = 0; q < 4; q++) c[mt][nt][q] = 0.f;

    int ar = tid >> 1, acb = (tid & 1) * 16;   // A stage: 128 rows x 32 k
    int br = tid >> 3, bcb = (tid & 7) * 16;   // B stage: 32 k x 128 cols

    for (int kc = 0; kc < 128; kc += 32) {
        {
            int grow = m0 + ar;
#pragma unroll
            for (int q = 0; q < 4; q++) {
                float4 v = (grow < M)
                    ? *(const float4*)&A[(size_t)grow * 128 + kc + acb + q * 4]
                    : make_float4(0.f, 0.f, 0.f, 0.f);
                uint4 u = make_uint4(f2tf(v.x), f2tf(v.y), f2tf(v.z), f2tf(v.w));
                *(uint4*)&As[ar * AS_STR + acb + q * 4] = u;
            }
#pragma unroll
            for (int q = 0; q < 4; q++) {
                float4 v = *(const float4*)&B[(size_t)(kc + br) * 128 + bcb + q * 4];
                uint4 u = make_uint4(f2tf(v.x), f2tf(v.y), f2tf(v.z), f2tf(v.w));
                *(uint4*)&Bs[br * BS_STR + bcb + q * 4] = u;
            }
        }
        __syncthreads();
#pragma unroll
        for (int ks = 0; ks < 4; ks++) {
            int kb = ks * 8;
            unsigned a[2][4], b[8][2];
#pragma unroll
            for (int mt = 0; mt < 2; mt++) {
                int r = wm * 32 + mt * 16 + gid;
                a[mt][0] = As[r * AS_STR + kb + tig];
                a[mt][1] = As[(r + 8) * AS_STR + kb + tig];
                a[mt][2] = As[r * AS_STR + kb + tig + 4];
                a[mt][3] = As[(r + 8) * AS_STR + kb + tig + 4];
            }
#pragma unroll
            for (int nt = 0; nt < 8; nt++) {
                int bc = wn * 64 + nt * 8 + gid;
                b[nt][0] = Bs[(kb + tig) * BS_STR + bc];
                b[nt][1] = Bs[(kb + tig + 4) * BS_STR + bc];
            }
#pragma unroll
            for (int mt = 0; mt < 2; mt++)
#pragma unroll
                for (int nt = 0; nt < 8; nt++) mma8(c[mt][nt], a[mt], b[nt]);
        }
        __syncthreads();
    }

#pragma unroll
    for (int mt = 0; mt < 2; mt++) {
        int r = m0 + wm * 32 + mt * 16 + gid;
#pragma unroll
        for (int nt = 0; nt < 8; nt++) {
            int col = wn * 64 + nt * 8 + 2 * tig;
            float2 v0 = make_float2(c[mt][nt][0], c[mt][nt][1]);
            float2 v1 = make_float2(c[mt][nt][2], c[mt][nt][3]);
            if (relu) {
                v0.x = fmaxf(v0.x, 0.f); v0.y = fmaxf(v0.y, 0.f);
                v1.x = fmaxf(v1.x, 0.f); v1.y = fmaxf(v1.y, 0.f);
            }
            if (r < M)     *(float2*)&C[(size_t)r * 128 + col] = v0;
            if (r + 8 < M) *(float2*)&C[(size_t)(r + 8) * 128 + col] = v1;
        }
    }
}

// ---------------- CSR gather-aggregation: warp per node, float4 lanes ----------------
__device__ __forceinline__ void agg_node(const float* __restrict__ in, int n, int lane,
                                         float4& r) {
    int s = g_rowptr[n], e = g_rowptr[n + 1];
    float4 a0 = make_float4(0.f, 0.f, 0.f, 0.f), a1 = a0, a2 = a0, a3 = a0;
    int i = s;
    for (; i + 4 <= e; i += 4) {
        int c0 = g_col[i], c1 = g_col[i + 1], c2 = g_col[i + 2], c3 = g_col[i + 3];
        float4 v0 = *(const float4*)&in[(size_t)c0 * 128 + lane * 4];
        float4 v1 = *(const float4*)&in[(size_t)c1 * 128 + lane * 4];
        float4 v2 = *(const float4*)&in[(size_t)c2 * 128 + lane * 4];
        float4 v3 = *(const float4*)&in[(size_t)c3 * 128 + lane * 4];
        a0.x += v0.x; a0.y += v0.y; a0.z += v0.z; a0.w += v0.w;
        a1.x += v1.x; a1.y += v1.y; a1.z += v1.z; a1.w += v1.w;
        a2.x += v2.x; a2.y += v2.y; a2.z += v2.z; a2.w += v2.w;
        a3.x += v3.x; a3.y += v3.y; a3.z += v3.z; a3.w += v3.w;
    }
    for (; i < e; i++) {
        int c = g_col[i];
        float4 v = *(const float4*)&in[(size_t)c * 128 + lane * 4];
        a0.x += v.x; a0.y += v.y; a0.z += v.z; a0.w += v.w;
    }
    float inv = g_invdeg[n];
    r.x = (a0.x + a1.x + a2.x + a3.x) * inv;
    r.y = (a0.y + a1.y + a2.y + a3.y) * inv;
    r.z = (a0.z + a1.z + a2.z + a3.z) * inv;
    r.w = (a0.w + a1.w + a2.w + a3.w) * inv;
}

__global__ void k_agg(const float* __restrict__ in, float* __restrict__ out, int relu) {
    int n = blockIdx.x * 8 + (threadIdx.x >> 5);
    if (n >= N_NODES) return;
    int lane = threadIdx.x & 31;
    float4 r;
    agg_node(in, n, lane, r);
    if (relu) {
        r.x = fmaxf(r.x, 0.f); r.y = fmaxf(r.y, 0.f);
        r.z = fmaxf(r.z, 0.f); r.w = fmaxf(r.w, 0.f);
    }
    *(float4*)&out[(size_t)n * 128 + lane * 4] = r;
}

__global__ void k_agg_flagged(const float* __restrict__ in, float* __restrict__ out) {
    int n = blockIdx.x * 8 + (threadIdx.x >> 5);
    if (n >= N_NODES) return;
    if (!g_flag[n]) return;
    int lane = threadIdx.x & 31;
    float4 r;
    agg_node(in, n, lane, r);
    *(float4*)&out[(size_t)n * 128 + lane * 4] = r;
}

__global__ void k_agg_target(const float* __restrict__ in, const int* __restrict__ tgt,
                             float* __restrict__ out) {
    int b = blockIdx.x * 8 + (threadIdx.x >> 5);
    if (b >= T_NODES) return;
    int lane = threadIdx.x & 31;
    int n = tgt[b];
    float4 r;
    agg_node(in, n, lane, r);
    *(float4*)&out[(size_t)b * 128 + lane * 4] = r;
}

// ---------------- predictor stage 1 (tf32 MMA) ----------------
// hidden[64,256] = relu(feats[64,136] @ W + zb); W = [Wf rows | Wp1 rows 192..199]
#define FS_STR 140
#define WS_STR 264
__global__ void __launch_bounds__(256)
k_pred1(const float* __restrict__ m, const int* __restrict__ pair_s,
        const int* __restrict__ pair_t, const int* __restrict__ tgt,
        const float* __restrict__ mask, const float* __restrict__ Wp1) {
    int r0 = blockIdx.x * 64;
    int tid = threadIdx.x;
    int any = __syncthreads_or(tid < 64 && mask[r0 + tid] != 0.f);
    if (!any) return;  // pred2 zero-fills these rows

    __shared__ unsigned feats[64 * FS_STR];
    __shared__ unsigned ws[8 * WS_STR];

#pragma unroll
    for (int i = 0; i < 8; i++) {
        int idx = tid + i * 256;
        int r = idx >> 5, q = (idx & 31) << 2;
        int sN = pair_s[r0 + r];
        float4 v = *(const float4*)&m[(size_t)sN * 128 + q];
        uint4 u = make_uint4(f2tf(v.x), f2tf(v.y), f2tf(v.z), f2tf(v.w));
        *(uint4*)&feats[r * FS_STR + q] = u;
    }
    if (tid < 64) {
        int sN = pair_s[r0 + tid];
        int tN = tgt[pair_t[r0 + tid]];
        float4 ps = *(const float4*)&g_pe[sN * 4];
        float4 pt = *(const float4*)&g_pe[tN * 4];
        *(uint4*)&feats[tid * FS_STR + 128] =
            make_uint4(f2tf(ps.x), f2tf(ps.y), f2tf(ps.z), f2tf(ps.w));
        *(uint4*)&feats[tid * FS_STR + 132] =
            make_uint4(f2tf(pt.x), f2tf(pt.y), f2tf(pt.z), f2tf(pt.w));
    }

    int lane = tid & 31, wid = tid >> 5;
    int wm = wid & 1, wn = wid >> 1;       // rows wm*32, cols wn*64
    int gid = lane >> 2, tig = lane & 3;

    float c[2][8][4];
#pragma unroll
    for (int mt = 0; mt < 2; mt++)
#pragma unroll
        for (int nt = 0; nt < 8; nt++)
#pragma unroll
            for (int q = 0; q < 4; q++) c[mt][nt][q] = 0.f;

    for (int ch = 0; ch < 17; ch++) {
        {
            int kk = tid >> 5, j = (tid & 31) << 3;
            const float* src = (ch < 16) ? &g_wf[(ch * 8 + kk) * 256 + j]
                                         : &Wp1[(192 + kk) * 256 + j];
            float4 v0 = *(const float4*)src;
            float4 v1 = *(const float4*)(src + 4);
            *(uint4*)&ws[kk * WS_STR + j] =
                make_uint4(f2tf(v0.x), f2tf(v0.y), f2tf(v0.z), f2tf(v0.w));
            *(uint4*)&ws[kk * WS_STR + j + 4] =
                make_uint4(f2tf(v1.x), f2tf(v1.y), f2tf(v1.z), f2tf(v1.w));
        }
        __syncthreads();
        int kb = ch * 8;
        unsigned a[2][4], b[8][2];
#pragma unroll
        for (int mt = 0; mt < 2; mt++) {
            int r = wm * 32 + mt * 16 + gid;
            a[mt][0] = feats[r * FS_STR + kb + tig];
            a[mt][1] = feats[(r + 8) * FS_STR + kb + tig];
            a[mt][2] = feats[r * FS_STR + kb + tig + 4];
            a[mt][3] = feats[(r + 8) * FS_STR + kb + tig + 4];
        }
#pragma unroll
        for (int nt = 0; nt < 8; nt++) {
            int bc = wn * 64 + nt * 8 + gid;
            b[nt][0] = ws[tig * WS_STR + bc];
            b[nt][1] = ws[(tig + 4) * WS_STR + bc];
        }
#pragma unroll
        for (int mt = 0; mt < 2; mt++)
#pragma unroll
            for (int nt = 0; nt < 8; nt++) mma8(c[mt][nt], a[mt], b[nt]);
        __syncthreads();
    }

#pragma unroll
    for (int mt = 0; mt < 2; mt++) {
        int r = r0 + wm * 32 + mt * 16 + gid;
#pragma unroll
        for (int nt = 0; nt < 8; nt++) {
            int col = wn * 64 + nt * 8 + 2 * tig;
            float2 zbv = *(const float2*)&g_zb[col];
            float2 v0 = make_float2(fmaxf(c[mt][nt][0] + zbv.x, 0.f),
                                    fmaxf(c[mt][nt][1] + zbv.y, 0.f));
            float2 v1 = make_float2(fmaxf(c[mt][nt][2] + zbv.x, 0.f),
                                    fmaxf(c[mt][nt][3] + zbv.y, 0.f));
            *(float2*)&g_hidden[(size_t)r * 256 + col] = v0;
            *(float2*)&g_hidden[(size_t)(r + 8) * 256 + col] = v1;
        }
    }
}

// ---------------- predictor stage 2 (tf32 MMA): pred = (hidden @ Wp2 + bp2) * mask --
#define HS_STR 20
#define W2_STR 136
__global__ void __launch_bounds__(256)
k_pred2(const float* __restrict__ Wp2, const float* __restrict__ bp2,
        const float* __restrict__ mask, float* __restrict__ out) {
    int r0 = blockIdx.x * 64;
    int tid = threadIdx.x;
    __shared__ float ms[64];
    if (tid < 64) ms[tid] = mask[r0 + tid];
    int any = __syncthreads_or(tid < 64 && mask[r0 + tid] != 0.f);
    if (!any) {
        float4 zero = make_float4(0.f, 0.f, 0.f, 0.f);
#pragma unroll
        for (int i = 0; i < 8; i++) {
            int idx = tid + i * 256;
            *(float4*)&out[(size_t)r0 * 128 + idx * 4] = zero;
        }
        return;
    }

    __shared__ unsigned As[64 * HS_STR];
    __shared__ unsigned ws2[16 * W2_STR];

    int lane = tid & 31, wid = tid >> 5;
    int wm = wid & 1, wn = wid >> 1;       // rows wm*32, cols wn*32
    int gid = lane >> 2, tig = lane & 3;

    float c[2][4][4];
#pragma unroll
    for (int mt = 0; mt < 2; mt++)
#pragma unroll
        for (int nt = 0; nt < 4; nt++)
#pragma unroll
            for (int q = 0; q < 4; q++) c[mt][nt][q] = 0.f;

    for (int ch = 0; ch < 16; ch++) {
        {
            int r = tid >> 2, kq = (tid & 3) << 2;
            float4 v = *(const float4*)&g_hidden[(size_t)(r0 + r) * 256 + ch * 16 + kq];
            *(uint4*)&As[r * HS_STR + kq] =
                make_uint4(f2tf(v.x), f2tf(v.y), f2tf(v.z), f2tf(v.w));
#pragma unroll
            for (int h = 0; h < 2; h++) {
                int kk = (tid >> 5) + h * 8;
                int j = (tid & 31) << 2;
                float4 w = *(const float4*)&Wp2[(size_t)(ch * 16 + kk) * 128 + j];
                *(uint4*)&ws2[kk * W2_STR + j] =
                    make_uint4(f2tf(w.x), f2tf(w.y), f2tf(w.z), f2tf(w.w));
            }
        }
        __syncthreads();
#pragma unroll
        for (int ks = 0; ks < 2; ks++) {
            int kb = ks * 8;
            unsigned a[2][4], b[4][2];
#pragma unroll
            for (int mt = 0; mt < 2; mt++) {
                int r = wm * 32 + mt * 16 + gid;
                a[mt][0] = As[r * HS_STR + kb + tig];
                a[mt][1] = As[(r + 8) * HS_STR + kb + tig];
                a[mt][2] = As[r * HS_STR + kb + tig + 4];
                a[mt][3] = As[(r + 8) * HS_STR + kb + tig + 4];
            }
#pragma unroll
            for (int nt = 0; nt < 4; nt++) {
                int bc = wn * 32 + nt * 8 + gid;
                b[nt][0] = ws2[(kb + tig) * W2_STR + bc];
                b[nt][1] = ws2[(kb + tig + 4) * W2_STR + bc];
            }
#pragma unroll
            for (int mt = 0; mt < 2; mt++)
#pragma unroll
                for (int nt = 0; nt < 4; nt++) mma8(c[mt][nt], a[mt], b[nt]);
        }
        __syncthreads();
    }

#pragma unroll
    for (int mt = 0; mt < 2; mt++) {
        int lr = wm * 32 + mt * 16 + gid;
        float m0v = ms[lr], m1v = ms[lr + 8];
#pragma unroll
        for (int nt = 0; nt < 4; nt++) {
            int col = wn * 32 + nt * 8 + 2 * tig;
            float2 bb = *(const float2*)&bp2[col];
            float2 v0 = make_float2((c[mt][nt][0] + bb.x) * m0v,
                                    (c[mt][nt][1] + bb.y) * m0v);
            float2 v1 = make_float2((c[mt][nt][2] + bb.x) * m1v,
                                    (c[mt][nt][3] + bb.y) * m1v);
            *(float2*)&out[(size_t)(r0 + lr) * 128 + col] = v0;
            *(float2*)&out[(size_t)(r0 + lr + 8) * 128 + col] = v1;
        }
    }
}

// ---------------- launch ----------------
extern "C" void kernel_launch(void* const* d_in, const int* in_sizes, int n_in,
                              void* d_out, int out_size) {
    const float* x            = (const float*)d_in[0];
    const float* masked_x     = (const float*)d_in[1];
    const float* pos_enc      = (const float*)d_in[2];
    const int*   edge_src     = (const int*)d_in[3];
    const int*   edge_dst     = (const int*)d_in[4];
    const int*   target_nodes = (const int*)d_in[5];
    const int*   pair_t       = (const int*)d_in[6];
    const int*   pair_s       = (const int*)d_in[7];
    const float* pair_mask    = (const float*)d_in[8];
    const float* W1t          = (const float*)d_in[9];
    const float* W2t          = (const float*)d_in[10];
    const float* W1c          = (const float*)d_in[11];
    const float* W2c          = (const float*)d_in[12];
    const float* Wpe          = (const float*)d_in[13];
    const float* z            = (const float*)d_in[14];
    const float* Wp1          = (const float*)d_in[15];
    const float* bp1          = (const float*)d_in[16];
    const float* Wp2          = (const float*)d_in[17];
    const float* bp2          = (const float*)d_in[18];
    float* out = (float*)d_out;

    float *buf1, *buf2, *tbuf;
    cudaGetSymbolAddress((void**)&buf1, g_buf1);
    cudaGetSymbolAddress((void**)&buf2, g_buf2);
    cudaGetSymbolAddress((void**)&tbuf, g_tbuf);

    const int TPB = 256;
    int gridN = (N_NODES + TPB - 1) / TPB;
    int gridE = (N_EDGES + TPB - 1) / TPB;
    int gridM = (N_NODES + 127) / 128;
    int gridA = (N_NODES + 7) / 8;

    // CSR build, with the first big GEMM hoisted to launch slot 4 for profiling.
    // (agg commutes with right-mult: gemm-then-agg == agg-then-gemm.)
    k_zero_cnt<<<gridN, TPB>>>();
    k_count<<<gridE, TPB>>>(edge_dst);
    k_scan<<<1, 1024>>>();
    k_gemm_tf32<<<gridM, 256>>>(x, W1t, buf2, N_NODES, 0);     // x @ W1t
    k_prep<<<gridN, TPB>>>();
    k_fill<<<gridE, TPB>>>(edge_src, edge_dst);
    k_flag<<<P_PAIRS / TPB, TPB>>>(pair_s, pair_mask);

    // tiny precomputes
    k_pe<<<gridN, TPB>>>(pos_enc, Wpe);
    k_zb<<<1, HP>>>(z, Wp1, bp1);
    k_wf<<<DIM, HP>>>(W2c, Wp1);

    // target GCN: h = relu(agg(xW1)) ; out_emb = agg(h)[targets] @ W2t
    k_agg<<<gridA, 256>>>(buf2, buf1, 1);
    k_agg_target<<<(T_NODES + 7) / 8, 256>>>(buf1, target_nodes, tbuf);
    k_gemm_tf32<<<T_NODES / 128, 256>>>(tbuf, W2t, out + (size_t)P_PAIRS * DOUT,
                                        T_NODES, 0);

    // context GCN: h_c = relu(agg(mxW1c)) ; m = agg(h_c) restricted to flagged nodes
    k_gemm_tf32<<<gridM, 256>>>(masked_x, W1c, buf2, N_NODES, 0);
    k_agg<<<gridA, 256>>>(buf2, buf1, 1);
    k_agg_flagged<<<gridA, 256>>>(buf1, buf2);   // m -> buf2

    // predictor MLP (64-row tiles, mask-tile skipping)
    k_pred1<<<P_PAIRS / 64, 256>>>(buf2, pair_s, pair_t, target_nodes, pair_mask, Wp1);
    k_pred2<<<P_PAIRS / 64, 256>>>(Wp2, bp2, pair_mask, out);
}